// round 14
// baseline (speedup 1.0000x reference)
#include <cuda_runtime.h>
#include <cuda_fp16.h>
#include <cstdint>
#include <math.h>

#define S_TOK 8192
#define HID   1024
#define INTR  4096
#define NE    8
#define CAP   1024

#define BM 128
#define BN 128
#define BK 64               // fp16 elements per k-tile
#define A_TILE_BYTES 16384  // 128 rows x 128B
#define B_TILE_BYTES 16384  // 64 rows x 256B
#define STAGE_BYTES 32768
#define NSTAGE 3
#define SMEM_BYTES  (NSTAGE * STAGE_BYTES)   // 96KB -> 2 CTAs/SM

// ---------------- device scratch (no allocation allowed) ----------------
__device__ __half g_attn[S_TOK * HID];
__device__ __half g_h[NE * CAP * INTR];
__device__ float  g_eo[NE * CAP * HID];
__device__ __half g_rh[S_TOK * INTR];
__device__ __half g_iw[NE * HID * INTR];   // [e][K=HID][N=INTR] fp16 (original layout)
__device__ __half g_ow[NE * INTR * HID];   // [e][K=INTR][N=HID]
__device__ __half g_ri[HID * INTR];
__device__ __half g_ro[INTR * HID];
__device__ int   g_expidx[S_TOK];
__device__ int   g_dest[S_TOK];
__device__ int   g_tos[NE * CAP];
__device__ float g_gate[S_TOK];
__device__ float g_coef0[S_TOK];
__device__ float g_coef1[S_TOK];

// ---------------- helpers ----------------
__device__ __forceinline__ float gelu_tanh(float x) {
    float x3 = x * x * x;
    return 0.5f * x * (1.f + tanhf(0.7978845608028654f * (x + 0.044715f * x3)));
}

__device__ __forceinline__ uint32_t smem_u32(const void* p) {
    uint32_t a;
    asm("{ .reg .u64 t; cvta.to.shared.u64 t, %1; cvt.u32.u64 %0, t; }" : "=r"(a) : "l"(p));
    return a;
}

__device__ __forceinline__ void ldsm_x4(uint32_t (&r)[4], uint32_t addr) {
    asm volatile("ldmatrix.sync.aligned.m8n8.x4.shared.b16 {%0,%1,%2,%3}, [%4];"
                 : "=r"(r[0]), "=r"(r[1]), "=r"(r[2]), "=r"(r[3]) : "r"(addr));
}

__device__ __forceinline__ void ldsm_x4_t(uint32_t (&r)[4], uint32_t addr) {
    asm volatile("ldmatrix.sync.aligned.m8n8.x4.trans.shared.b16 {%0,%1,%2,%3}, [%4];"
                 : "=r"(r[0]), "=r"(r[1]), "=r"(r[2]), "=r"(r[3]) : "r"(addr));
}

__device__ __forceinline__ void mma16816(float (&c)[4], const uint32_t (&a)[4],
                                         const uint32_t* b) {
    asm volatile(
        "mma.sync.aligned.m16n8k16.row.col.f32.f16.f16.f32 "
        "{%0,%1,%2,%3}, {%4,%5,%6,%7}, {%8,%9}, {%0,%1,%2,%3};"
        : "+f"(c[0]), "+f"(c[1]), "+f"(c[2]), "+f"(c[3])
        : "r"(a[0]), "r"(a[1]), "r"(a[2]), "r"(a[3]), "r"(b[0]), "r"(b[1]));
}

#define CP_ASYNC16(sm, gm) asm volatile("cp.async.cg.shared.global [%0], [%1], 16;" :: "r"(sm), "l"(gm))
// register src-size form: src_size=0 -> 16B zero-fill (no bytes read)
#define CP_ASYNC16Z(sm, gm, sz) asm volatile("cp.async.cg.shared.global [%0], [%1], 16, %2;" :: "r"(sm), "l"(gm), "r"(sz))
#define CP_COMMIT()        asm volatile("cp.async.commit_group;" ::: "memory")
#define CP_WAIT(n)         asm volatile("cp.async.wait_group %0;" :: "n"(n) : "memory")

// ===========================================================================
// LayerNorm + gate logits + res_coef; emits attn as fp16
// ===========================================================================
__global__ void ln_gate_kernel(const float* __restrict__ x,
                               const float* __restrict__ nw,
                               const float* __restrict__ nb,
                               const float* __restrict__ wg,
                               const float* __restrict__ res_coef) {
    __shared__ float row[HID];
    __shared__ float rs[10], rq[10];
    __shared__ float dots[10];
    __shared__ float s_mean, s_rstd;

    const int s = blockIdx.x;
    const int tid = threadIdx.x;
    const int lane = tid & 31;
    const int w = tid >> 5;

    const float* xr = x + (size_t)s * HID;
    float sum = 0.f, sq = 0.f;
    for (int i = tid; i < HID; i += 320) {
        float v = xr[i];
        row[i] = v;
        sum += v; sq += v * v;
    }
    #pragma unroll
    for (int o = 16; o > 0; o >>= 1) {
        sum += __shfl_down_sync(0xffffffffu, sum, o);
        sq  += __shfl_down_sync(0xffffffffu, sq,  o);
    }
    if (lane == 0) { rs[w] = sum; rq[w] = sq; }
    __syncthreads();
    if (tid == 0) {
        float ts = 0.f, tq = 0.f;
        #pragma unroll
        for (int i = 0; i < 10; i++) { ts += rs[i]; tq += rq[i]; }
        float mean = ts * (1.f / HID);
        float var  = tq * (1.f / HID) - mean * mean;
        s_mean = mean;
        s_rstd = rsqrtf(var + 1e-12f);
    }
    __syncthreads();
    const float mean = s_mean, rstd = s_rstd;
    for (int i = tid; i < HID; i += 320) {
        float v = (row[i] - mean) * rstd * nw[i] + nb[i];
        row[i] = v;
        g_attn[(size_t)s * HID + i] = __float2half_rn(v);
    }
    __syncthreads();

    float d = 0.f;
    if (w < 8) {
        for (int m = lane; m < HID; m += 32) d += row[m] * wg[m * NE + w];
    } else {
        int c = w - 8;
        for (int m = lane; m < HID; m += 32) d += row[m] * res_coef[m * 2 + c];
    }
    #pragma unroll
    for (int o = 16; o > 0; o >>= 1) d += __shfl_down_sync(0xffffffffu, d, o);
    if (lane == 0) dots[w] = d;
    __syncthreads();

    if (tid == 0) {
        float mx = dots[0]; int am = 0;
        #pragma unroll
        for (int e = 1; e < 8; e++) if (dots[e] > mx) { mx = dots[e]; am = e; }
        float se = 0.f;
        #pragma unroll
        for (int e = 0; e < 8; e++) se += expf(dots[e] - mx);
        g_expidx[s] = am;
        g_gate[s] = 1.f / se;
        float a = dots[8], b = dots[9];
        float m2 = fmaxf(a, b);
        float ea = expf(a - m2), eb = expf(b - m2);
        float inv = 1.f / (ea + eb);
        g_coef0[s] = ea * inv;
        g_coef1[s] = eb * inv;
    }
}

// ===========================================================================
__global__ void scan_kernel() {
    const int tid = threadIdx.x;
    for (int i = tid; i < NE * CAP; i += 256) g_tos[i] = -1;
    __syncthreads();
    const int lane = tid & 31;
    const int e = tid >> 5;
    int count = 0;
    for (int base = 0; base < S_TOK; base += 32) {
        int s = base + lane;
        bool sel = (g_expidx[s] == e);
        unsigned mask = __ballot_sync(0xffffffffu, sel);
        if (sel) {
            int c = count + __popc(mask & ((1u << lane) - 1u));
            if (c < CAP) {
                g_dest[s] = e * CAP + c;
                g_tos[e * CAP + c] = s;
            } else {
                g_dest[s] = -1;
            }
        }
        count += __popc(mask);
    }
}

// ===========================================================================
// Streaming fp32 -> fp16 convert, one tensor per launch (MLP=8).
// Block b covers [b*8192, (b+1)*8192); thread: 4 chunks of 8 spaced 2048.
// ===========================================================================
__global__ __launch_bounds__(256) void wconv_kernel(const float* __restrict__ W,
                                                    __half* __restrict__ T) {
    const size_t base = (size_t)blockIdx.x * 8192 + (size_t)threadIdx.x * 8;
    float4 a[4], c[4];
    #pragma unroll
    for (int j = 0; j < 4; j++) {
        a[j] = *(const float4*)(W + base + (size_t)j * 2048);
        c[j] = *(const float4*)(W + base + (size_t)j * 2048 + 4);
    }
    #pragma unroll
    for (int j = 0; j < 4; j++) {
        __half h[8];
        h[0] = __float2half_rn(a[j].x); h[1] = __float2half_rn(a[j].y);
        h[2] = __float2half_rn(a[j].z); h[3] = __float2half_rn(a[j].w);
        h[4] = __float2half_rn(c[j].x); h[5] = __float2half_rn(c[j].y);
        h[6] = __float2half_rn(c[j].z); h[7] = __float2half_rn(c[j].w);
        *(uint4*)(T + base + (size_t)j * 2048) = *(uint4*)h;
    }
}

// ===========================================================================
// mma.sync fp16 GEMM body: C = epilogue(A @ B + bias)
// A: [M,K] K-major fp16 (GATHER=1: rows indirected through g_tos, zero-fill).
// B: [K,N] N-major fp16 (trans-ldmatrix).
// BM=BN=128, BK=64, 256 threads (8 warps, 2m x 4n), warp tile 64x32.
// 3-stage cp.async pipeline, ONE barrier per stage, 96KB smem -> 2 CTAs/SM.
// ACT=0: fp32 out. ACT=1: gelu -> fp16 out.
// ACT=2: fused final combine: out = x + c0*(acc+bias) + c1*gate*eo[dest]
// ===========================================================================
template <int ACT, int GATHER>
__device__ __forceinline__
void gemm_body(const __half* __restrict__ A, const __half* __restrict__ B,
               const float* __restrict__ bias,
               float* __restrict__ Cf, __half* __restrict__ Ch,
               const float* __restrict__ Xres, const float* __restrict__ Eo,
               int M, int N, int K, int bx, int by, int bzi) {
    extern __shared__ char smem[];
    const uint32_t sbase = smem_u32(smem);
    const int tid = threadIdx.x;
    const int lane = tid & 31;
    const int wid = tid >> 5;
    const int wm = wid >> 2;          // 0..1 -> warp row (64 rows each)
    const int wn = wid & 3;           // 0..3 -> warp col (32 cols each)
    const long bz = bzi;
    const int m0 = by * BM;
    const int n0 = bx * BN;

    const __half* srcA;
    long atok[4];          // per-thread A-row base offsets (elements)
    uint32_t asz[4];       // cp.async src sizes (16 or 0)
    if (GATHER) {
        srcA = A;          // A = g_attn base; rows indirected
        #pragma unroll
        for (int i = 0; i < 4; i++) {
            int row = (tid >> 3) + i * 32;
            int t = g_tos[bz * CAP + m0 + row];
            atok[i] = (t >= 0) ? (long)t * K : 0;
            asz[i] = (t >= 0) ? 16u : 0u;
        }
    } else {
        srcA = A + bz * (long)M * K + (size_t)m0 * K;
        #pragma unroll
        for (int i = 0; i < 4; i++) {
            atok[i] = (long)((tid >> 3) + i * 32) * K;
            asz[i] = 16u;
        }
    }
    const __half* srcB = B + bz * (long)K * N + n0;
    bias += bz * (long)N;

    float acc[4][4][4];
    #pragma unroll
    for (int a = 0; a < 4; a++)
        #pragma unroll
        for (int b = 0; b < 4; b++)
            #pragma unroll
            for (int c = 0; c < 4; c++) acc[a][b][c] = 0.f;

    const int NT = K / BK;

    auto load_stage = [&](int st, int kt) {
        const uint32_t stb = sbase + (uint32_t)st * STAGE_BYTES;
        // A tile: 128 rows x 128B (rows = m)
        {
            const __half* gA = srcA + kt + (tid & 7) * 8;
            #pragma unroll
            for (int i = 0; i < 4; i++) {
                int row = (tid >> 3) + i * 32;
                uint32_t sm = stb + (uint32_t)(row * 128 + (((tid & 7) ^ (row & 7)) << 4));
                CP_ASYNC16Z(sm, gA + atok[i], asz[i]);
            }
        }
        // B tile: 64 rows x 256B (rows = k, 128 fp16 n-cols per row)
        {
            const __half* gB = srcB + (size_t)kt * N + (tid & 15) * 8;
            const int r0 = tid >> 4;
            #pragma unroll
            for (int i = 0; i < 4; i++) {
                int row = r0 + i * 16;
                uint32_t sm = stb + A_TILE_BYTES +
                              (uint32_t)(row * 256 + (((tid & 15) ^ (row & 7)) << 4));
                CP_ASYNC16(sm, gB + (size_t)row * N);
            }
        }
    };

    // prime NSTAGE-1 stages
    #pragma unroll
    for (int p = 0; p < NSTAGE - 1; p++) {
        if (p < NT) { load_stage(p, p * BK); CP_COMMIT(); }
    }

    for (int s = 0; s < NT; s++) {
        if (s + NSTAGE - 1 < NT) CP_WAIT(NSTAGE - 2);
        else if (s + NSTAGE - 2 < NT) CP_WAIT(NSTAGE - 3);
        else CP_WAIT(0);
        // Single barrier per stage: orders (a) stage s data visible to all,
        // (b) all warps done computing stage s-1 before anyone overwrites
        // buffer (s+2)%3 (last read at stage s-1).
        __syncthreads();

        if (s + NSTAGE - 1 < NT) {
            load_stage((s + NSTAGE - 1) % NSTAGE, (s + NSTAGE - 1) * BK);
            CP_COMMIT();
        }

        const uint32_t stb = sbase + (uint32_t)(s % NSTAGE) * STAGE_BYTES;
        const uint32_t Ab = stb, Bb = stb + A_TILE_BYTES;

        const int g = lane >> 3;       // ldmatrix address group
        const int li = lane & 7;

        #pragma unroll
        for (int kk = 0; kk < 4; kk++) {
            uint32_t af[4][4];
            {
                const int arow_b = wm * 64 + (g & 1) * 8 + li;
                const int ach = kk * 2 + (g >> 1);
                #pragma unroll
                for (int mf = 0; mf < 4; mf++) {
                    int r = arow_b + mf * 16;
                    uint32_t off = (uint32_t)(r * 128 + ((ach ^ (r & 7)) << 4));
                    ldsm_x4(af[mf], Ab + off);
                }
            }
            uint32_t bf[4][2];
            {
                const int kr = kk * 16 + (g & 1) * 8 + li;
                #pragma unroll
                for (int nb = 0; nb < 2; nb++) {
                    const int c = wn * 4 + nb * 2 + (g >> 1);   // 16B chunk (8 fp16 cols)
                    uint32_t off = (uint32_t)(kr * 256 + ((c ^ (kr & 7)) << 4));
                    uint32_t t4[4];
                    ldsm_x4_t(t4, Bb + off);
                    bf[nb * 2][0] = t4[0]; bf[nb * 2][1] = t4[1];
                    bf[nb * 2 + 1][0] = t4[2]; bf[nb * 2 + 1][1] = t4[3];
                }
            }
            #pragma unroll
            for (int mf = 0; mf < 4; mf++)
                #pragma unroll
                for (int nf = 0; nf < 4; nf++)
                    mma16816(acc[mf][nf], af[mf], bf[nf]);
        }
    }

    // ---- epilogue ----
    const int mrow = m0 + wm * 64 + (lane >> 2);
    const int ncol0 = n0 + wn * 32 + (lane & 3) * 2;
    #pragma unroll
    for (int nf = 0; nf < 4; nf++) {
        const int n = ncol0 + nf * 8;
        const float bv0 = bias[n], bv1 = bias[n + 1];
        #pragma unroll
        for (int mf = 0; mf < 4; mf++) {
            const float* c = acc[mf][nf];
            const int m_a = mrow + mf * 16;
            const int m_b = m_a + 8;
            if (ACT == 1) {
                float v00 = gelu_tanh(c[0] + bv0), v01 = gelu_tanh(c[1] + bv1);
                float v10 = gelu_tanh(c[2] + bv0), v11 = gelu_tanh(c[3] + bv1);
                uint32_t p0 = (uint32_t)__half_as_ushort(__float2half_rn(v00)) |
                              ((uint32_t)__half_as_ushort(__float2half_rn(v01)) << 16);
                uint32_t p1 = (uint32_t)__half_as_ushort(__float2half_rn(v10)) |
                              ((uint32_t)__half_as_ushort(__float2half_rn(v11)) << 16);
                *(uint32_t*)(Ch + bz * (long)M * N + (size_t)m_a * N + n) = p0;
                *(uint32_t*)(Ch + bz * (long)M * N + (size_t)m_b * N + n) = p1;
            } else if (ACT == 0) {
                float2 r0 = make_float2(c[0] + bv0, c[1] + bv1);
                float2 r1 = make_float2(c[2] + bv0, c[3] + bv1);
                *(float2*)(Cf + bz * (long)M * N + (size_t)m_a * N + n) = r0;
                *(float2*)(Cf + bz * (long)M * N + (size_t)m_b * N + n) = r1;
            } else {
                #pragma unroll
                for (int h = 0; h < 2; h++) {
                    const int m = h ? m_b : m_a;
                    const float va = h ? (c[2] + bv0) : (c[0] + bv0);
                    const float vb = h ? (c[3] + bv1) : (c[1] + bv1);
                    const int dd = g_dest[m];
                    const float c0 = g_coef0[m];
                    const float c1g = g_coef1[m] * g_gate[m];
                    float2 xv = *(const float2*)(Xres + (size_t)m * N + n);
                    float2 ev = make_float2(0.f, 0.f);
                    if (dd >= 0) ev = *(const float2*)(Eo + (size_t)dd * N + n);
                    float2 o;
                    o.x = xv.x + c0 * va + c1g * ev.x;
                    o.y = xv.y + c0 * vb + c1g * ev.y;
                    *(float2*)(Cf + (size_t)m * N + n) = o;
                }
            }
        }
    }
}

template <int ACT, int GATHER>
__global__ __launch_bounds__(256, 2)
void mma_gemm(const __half* __restrict__ A, const __half* __restrict__ B,
              const float* __restrict__ bias,
              float* __restrict__ Cf, __half* __restrict__ Ch,
              const float* __restrict__ Xres, const float* __restrict__ Eo,
              int M, int N, int K) {
    gemm_body<ACT, GATHER>(A, B, bias, Cf, Ch, Xres, Eo, M, N, K,
                           blockIdx.x, blockIdx.y, blockIdx.z);
}

// ===========================================================================
// Merged middle launch: expert GEMM2 (512 CTAs, long-K, scheduled first) +
// res GEMM1 (2048 CTAs) — independent work fills eG2's wave tail.
// ===========================================================================
__global__ __launch_bounds__(256, 2)
void mid_gemm(const __half* __restrict__ h, const __half* __restrict__ ow,
              const float* __restrict__ out_b, float* __restrict__ eo,
              const __half* __restrict__ attn, const __half* __restrict__ ri,
              const float* __restrict__ ri_b, __half* __restrict__ rh) {
    int b = blockIdx.x;
    if (b < 512) {
        // expert GEMM2: grid (HID/BN=8, CAP/BM=8, NE=8)
        gemm_body<0, 0>(h, ow, out_b, eo, nullptr, nullptr, nullptr,
                        CAP, HID, INTR, b & 7, (b >> 3) & 7, b >> 6);
    } else {
        // res GEMM1: grid (INTR/BN=32, S_TOK/BM=64)
        b -= 512;
        gemm_body<1, 0>(attn, ri, ri_b, nullptr, rh, nullptr, nullptr,
                        S_TOK, INTR, HID, b & 31, b >> 5, 0);
    }
}

// ===========================================================================
extern "C" void kernel_launch(void* const* d_in, const int* in_sizes, int n_in,
                              void* d_out, int out_size) {
    const float* x       = (const float*)d_in[0];
    const float* attn_nw = (const float*)d_in[1];
    const float* attn_nb = (const float*)d_in[2];
    const float* wg      = (const float*)d_in[3];
    const float* inter_w = (const float*)d_in[4];
    const float* inter_b = (const float*)d_in[5];
    const float* out_w   = (const float*)d_in[6];
    const float* out_b   = (const float*)d_in[7];
    const float* ri_w    = (const float*)d_in[8];
    const float* ri_b    = (const float*)d_in[9];
    const float* ro_w    = (const float*)d_in[10];
    const float* ro_b    = (const float*)d_in[11];
    const float* rcoef   = (const float*)d_in[12];
    float* out = (float*)d_out;

    cudaFuncSetAttribute((const void*)mma_gemm<1, 1>, cudaFuncAttributeMaxDynamicSharedMemorySize, SMEM_BYTES);
    cudaFuncSetAttribute((const void*)mma_gemm<2, 0>, cudaFuncAttributeMaxDynamicSharedMemorySize, SMEM_BYTES);
    cudaFuncSetAttribute((const void*)mid_gemm,       cudaFuncAttributeMaxDynamicSharedMemorySize, SMEM_BYTES);

    void *p_h, *p_eo, *p_attn, *p_rh;
    void *p_iw, *p_ow, *p_ri, *p_ro;
    cudaGetSymbolAddress(&p_h, g_h);
    cudaGetSymbolAddress(&p_eo, g_eo);
    cudaGetSymbolAddress(&p_attn, g_attn);
    cudaGetSymbolAddress(&p_rh, g_rh);
    cudaGetSymbolAddress(&p_iw, g_iw);
    cudaGetSymbolAddress(&p_ow, g_ow);
    cudaGetSymbolAddress(&p_ri, g_ri);
    cudaGetSymbolAddress(&p_ro, g_ro);

    // fork: weight converts on s2; eG1 only needs iw (eW1), mid/rG2 need rest (eW2)
    static cudaStream_t s2 = nullptr;
    static cudaEvent_t eF = nullptr, eW1 = nullptr, eW2 = nullptr;
    if (!s2) {
        cudaStreamCreateWithFlags(&s2, cudaStreamNonBlocking);
        cudaEventCreateWithFlags(&eF,  cudaEventDisableTiming);
        cudaEventCreateWithFlags(&eW1, cudaEventDisableTiming);
        cudaEventCreateWithFlags(&eW2, cudaEventDisableTiming);
    }
    cudaEventRecord(eF, 0);
    cudaStreamWaitEvent(s2, eF, 0);
    wconv_kernel<<<(NE * HID * INTR) / 8192, 256, 0, s2>>>(inter_w, (__half*)p_iw);
    cudaEventRecord(eW1, s2);
    wconv_kernel<<<(NE * INTR * HID) / 8192, 256, 0, s2>>>(out_w, (__half*)p_ow);
    wconv_kernel<<<(HID * INTR) / 8192, 256, 0, s2>>>(ri_w, (__half*)p_ri);
    wconv_kernel<<<(INTR * HID) / 8192, 256, 0, s2>>>(ro_w, (__half*)p_ro);
    cudaEventRecord(eW2, s2);

    ln_gate_kernel<<<S_TOK, 320>>>(x, attn_nw, attn_nb, wg, rcoef);
    scan_kernel<<<1, 256>>>();
    cudaStreamWaitEvent(0, eW1, 0);   // iw ready

    // expert GEMM1 + GELU with fused gather: h = gelu(attn[tos] @ iw + b)
    mma_gemm<1, 1><<<dim3(INTR / BN, CAP / BM, NE), 256, SMEM_BYTES>>>(
        (const __half*)p_attn, (const __half*)p_iw,
        inter_b, nullptr, (__half*)p_h, nullptr, nullptr, CAP, INTR, HID);
    cudaStreamWaitEvent(0, eW2, 0);   // ow/ri/ro ready
    // merged: expert GEMM2 (-> eo) + res GEMM1 (-> rh), independent work
    mid_gemm<<<512 + 2048, 256, SMEM_BYTES>>>(
        (const __half*)p_h, (const __half*)p_ow, out_b, (float*)p_eo,
        (const __half*)p_attn, (const __half*)p_ri, ri_b, (__half*)p_rh);
    // res GEMM2 + fused combine: out = x + c0*(rh@ro+b) + c1*gate*eo[dest]
    mma_gemm<2, 0><<<dim3(HID / BN, S_TOK / BM, 1), 256, SMEM_BYTES>>>(
        (const __half*)p_rh, (const __half*)p_ro,
        ro_b, out, nullptr, x, (const float*)p_eo, S_TOK, HID, INTR);
}

// round 15
// speedup vs baseline: 1.0454x; 1.0454x over previous
#include <cuda_runtime.h>
#include <cuda_fp16.h>
#include <cstdint>
#include <math.h>

#define S_TOK 8192
#define HID   1024
#define INTR  4096
#define NE    8
#define CAP   1024

#define BM 128
#define BN 128
#define BK 64               // fp16 elements per k-tile
#define A_TILE_BYTES 16384  // 128 rows x 128B
#define B_TILE_BYTES 16384  // 64 rows x 256B
#define STAGE_BYTES 32768
#define NSTAGE 3
#define SMEM_BYTES  (NSTAGE * STAGE_BYTES)   // 96KB -> 2 CTAs/SM

// ---------------- device scratch (no allocation allowed) ----------------
__device__ __half g_attn[S_TOK * HID];
__device__ __half g_h[NE * CAP * INTR];
__device__ float  g_eo[NE * CAP * HID];
__device__ __half g_rh[S_TOK * INTR];
__device__ __half g_iw[NE * HID * INTR];   // [e][K=HID][N=INTR] fp16 (original layout)
__device__ __half g_ow[NE * INTR * HID];   // [e][K=INTR][N=HID]
__device__ __half g_ri[HID * INTR];
__device__ __half g_ro[INTR * HID];
__device__ int   g_expidx[S_TOK];
__device__ int   g_dest[S_TOK];
__device__ int   g_tos[NE * CAP];
__device__ float g_gate[S_TOK];
__device__ float g_coef0[S_TOK];
__device__ float g_coef1[S_TOK];

// ---------------- helpers ----------------
__device__ __forceinline__ float gelu_tanh(float x) {
    float x3 = x * x * x;
    return 0.5f * x * (1.f + tanhf(0.7978845608028654f * (x + 0.044715f * x3)));
}

__device__ __forceinline__ uint32_t smem_u32(const void* p) {
    uint32_t a;
    asm("{ .reg .u64 t; cvta.to.shared.u64 t, %1; cvt.u32.u64 %0, t; }" : "=r"(a) : "l"(p));
    return a;
}

__device__ __forceinline__ void ldsm_x4(uint32_t (&r)[4], uint32_t addr) {
    asm volatile("ldmatrix.sync.aligned.m8n8.x4.shared.b16 {%0,%1,%2,%3}, [%4];"
                 : "=r"(r[0]), "=r"(r[1]), "=r"(r[2]), "=r"(r[3]) : "r"(addr));
}

__device__ __forceinline__ void ldsm_x4_t(uint32_t (&r)[4], uint32_t addr) {
    asm volatile("ldmatrix.sync.aligned.m8n8.x4.trans.shared.b16 {%0,%1,%2,%3}, [%4];"
                 : "=r"(r[0]), "=r"(r[1]), "=r"(r[2]), "=r"(r[3]) : "r"(addr));
}

__device__ __forceinline__ void mma16816(float (&c)[4], const uint32_t (&a)[4],
                                         const uint32_t* b) {
    asm volatile(
        "mma.sync.aligned.m16n8k16.row.col.f32.f16.f16.f32 "
        "{%0,%1,%2,%3}, {%4,%5,%6,%7}, {%8,%9}, {%0,%1,%2,%3};"
        : "+f"(c[0]), "+f"(c[1]), "+f"(c[2]), "+f"(c[3])
        : "r"(a[0]), "r"(a[1]), "r"(a[2]), "r"(a[3]), "r"(b[0]), "r"(b[1]));
}

#define CP_ASYNC16(sm, gm) asm volatile("cp.async.cg.shared.global [%0], [%1], 16;" :: "r"(sm), "l"(gm))
// register src-size form: src_size=0 -> 16B zero-fill (no bytes read)
#define CP_ASYNC16Z(sm, gm, sz) asm volatile("cp.async.cg.shared.global [%0], [%1], 16, %2;" :: "r"(sm), "l"(gm), "r"(sz))
#define CP_COMMIT()        asm volatile("cp.async.commit_group;" ::: "memory")
#define CP_WAIT(n)         asm volatile("cp.async.wait_group %0;" :: "n"(n) : "memory")

// ===========================================================================
// LayerNorm + gate logits + res_coef; emits attn as fp16
// ===========================================================================
__global__ void ln_gate_kernel(const float* __restrict__ x,
                               const float* __restrict__ nw,
                               const float* __restrict__ nb,
                               const float* __restrict__ wg,
                               const float* __restrict__ res_coef) {
    __shared__ float row[HID];
    __shared__ float rs[10], rq[10];
    __shared__ float dots[10];
    __shared__ float s_mean, s_rstd;

    const int s = blockIdx.x;
    const int tid = threadIdx.x;
    const int lane = tid & 31;
    const int w = tid >> 5;

    const float* xr = x + (size_t)s * HID;
    float sum = 0.f, sq = 0.f;
    for (int i = tid; i < HID; i += 320) {
        float v = xr[i];
        row[i] = v;
        sum += v; sq += v * v;
    }
    #pragma unroll
    for (int o = 16; o > 0; o >>= 1) {
        sum += __shfl_down_sync(0xffffffffu, sum, o);
        sq  += __shfl_down_sync(0xffffffffu, sq,  o);
    }
    if (lane == 0) { rs[w] = sum; rq[w] = sq; }
    __syncthreads();
    if (tid == 0) {
        float ts = 0.f, tq = 0.f;
        #pragma unroll
        for (int i = 0; i < 10; i++) { ts += rs[i]; tq += rq[i]; }
        float mean = ts * (1.f / HID);
        float var  = tq * (1.f / HID) - mean * mean;
        s_mean = mean;
        s_rstd = rsqrtf(var + 1e-12f);
    }
    __syncthreads();
    const float mean = s_mean, rstd = s_rstd;
    for (int i = tid; i < HID; i += 320) {
        float v = (row[i] - mean) * rstd * nw[i] + nb[i];
        row[i] = v;
        g_attn[(size_t)s * HID + i] = __float2half_rn(v);
    }
    __syncthreads();

    float d = 0.f;
    if (w < 8) {
        for (int m = lane; m < HID; m += 32) d += row[m] * wg[m * NE + w];
    } else {
        int c = w - 8;
        for (int m = lane; m < HID; m += 32) d += row[m] * res_coef[m * 2 + c];
    }
    #pragma unroll
    for (int o = 16; o > 0; o >>= 1) d += __shfl_down_sync(0xffffffffu, d, o);
    if (lane == 0) dots[w] = d;
    __syncthreads();

    if (tid == 0) {
        float mx = dots[0]; int am = 0;
        #pragma unroll
        for (int e = 1; e < 8; e++) if (dots[e] > mx) { mx = dots[e]; am = e; }
        float se = 0.f;
        #pragma unroll
        for (int e = 0; e < 8; e++) se += expf(dots[e] - mx);
        g_expidx[s] = am;
        g_gate[s] = 1.f / se;
        float a = dots[8], b = dots[9];
        float m2 = fmaxf(a, b);
        float ea = expf(a - m2), eb = expf(b - m2);
        float inv = 1.f / (ea + eb);
        g_coef0[s] = ea * inv;
        g_coef1[s] = eb * inv;
    }
}

// ===========================================================================
__global__ void scan_kernel() {
    const int tid = threadIdx.x;
    for (int i = tid; i < NE * CAP; i += 256) g_tos[i] = -1;
    __syncthreads();
    const int lane = tid & 31;
    const int e = tid >> 5;
    int count = 0;
    for (int base = 0; base < S_TOK; base += 32) {
        int s = base + lane;
        bool sel = (g_expidx[s] == e);
        unsigned mask = __ballot_sync(0xffffffffu, sel);
        if (sel) {
            int c = count + __popc(mask & ((1u << lane) - 1u));
            if (c < CAP) {
                g_dest[s] = e * CAP + c;
                g_tos[e * CAP + c] = s;
            } else {
                g_dest[s] = -1;
            }
        }
        count += __popc(mask);
    }
}

// ===========================================================================
// Merged streaming fp32 -> fp16 convert for all 4 weight tensors.
// Block b covers elements [b*8192, (b+1)*8192) of its tensor;
// each thread: 4 chunks of 8 elems spaced 2048 (MLP=8).
// ===========================================================================
#define IW_BLKS (NE * HID * INTR / 8192)   // 4096
#define OW_BLKS (NE * INTR * HID / 8192)   // 4096
#define RI_BLKS (HID * INTR / 8192)        // 512
#define RO_BLKS (INTR * HID / 8192)        // 512

__global__ __launch_bounds__(256) void wconv_all(const float* __restrict__ iw,
                                                 const float* __restrict__ ow,
                                                 const float* __restrict__ ri,
                                                 const float* __restrict__ ro) {
    int b = blockIdx.x;
    const float* W;
    __half* T;
    if (b < IW_BLKS)                        { W = iw; T = g_iw; }
    else if ((b -= IW_BLKS) < OW_BLKS)      { W = ow; T = g_ow; }
    else if ((b -= OW_BLKS) < RI_BLKS)      { W = ri; T = g_ri; }
    else                                    { b -= RI_BLKS; W = ro; T = g_ro; }
    const size_t base = (size_t)b * 8192 + (size_t)threadIdx.x * 8;
    float4 a[4], c[4];
    #pragma unroll
    for (int j = 0; j < 4; j++) {
        a[j] = *(const float4*)(W + base + (size_t)j * 2048);
        c[j] = *(const float4*)(W + base + (size_t)j * 2048 + 4);
    }
    #pragma unroll
    for (int j = 0; j < 4; j++) {
        __half h[8];
        h[0] = __float2half_rn(a[j].x); h[1] = __float2half_rn(a[j].y);
        h[2] = __float2half_rn(a[j].z); h[3] = __float2half_rn(a[j].w);
        h[4] = __float2half_rn(c[j].x); h[5] = __float2half_rn(c[j].y);
        h[6] = __float2half_rn(c[j].z); h[7] = __float2half_rn(c[j].w);
        *(uint4*)(T + base + (size_t)j * 2048) = *(uint4*)h;
    }
}

// ===========================================================================
// mma.sync fp16 GEMM body: C = epilogue(A @ B + bias)
// A: [M,K] K-major fp16 (GATHER=1: rows indirected through g_tos, zero-fill).
// B: [K,N] N-major fp16 (trans-ldmatrix).
// BM=BN=128, BK=64, 256 threads (8 warps, 2m x 4n), warp tile 64x32.
// 3-stage cp.async pipeline, ONE barrier per stage, 96KB smem -> 2 CTAs/SM.
// ACT=0: fp32 out. ACT=1: gelu -> fp16 out.
// ACT=2: fused final combine: out = x + c0*(acc+bias) + c1*gate*eo[dest]
// ===========================================================================
template <int ACT, int GATHER>
__device__ __forceinline__
void gemm_body(const __half* __restrict__ A, const __half* __restrict__ B,
               const float* __restrict__ bias,
               float* __restrict__ Cf, __half* __restrict__ Ch,
               const float* __restrict__ Xres, const float* __restrict__ Eo,
               int M, int N, int K, int bx, int by, int bzi) {
    extern __shared__ char smem[];
    const uint32_t sbase = smem_u32(smem);
    const int tid = threadIdx.x;
    const int lane = tid & 31;
    const int wid = tid >> 5;
    const int wm = wid >> 2;          // 0..1 -> warp row (64 rows each)
    const int wn = wid & 3;           // 0..3 -> warp col (32 cols each)
    const long bz = bzi;
    const int m0 = by * BM;
    const int n0 = bx * BN;

    const __half* srcA;
    long atok[4];          // per-thread A-row base offsets (elements)
    uint32_t asz[4];       // cp.async src sizes (16 or 0)
    if (GATHER) {
        srcA = A;          // A = g_attn base; rows indirected
        #pragma unroll
        for (int i = 0; i < 4; i++) {
            int row = (tid >> 3) + i * 32;
            int t = g_tos[bz * CAP + m0 + row];
            atok[i] = (t >= 0) ? (long)t * K : 0;
            asz[i] = (t >= 0) ? 16u : 0u;
        }
    } else {
        srcA = A + bz * (long)M * K + (size_t)m0 * K;
        #pragma unroll
        for (int i = 0; i < 4; i++) {
            atok[i] = (long)((tid >> 3) + i * 32) * K;
            asz[i] = 16u;
        }
    }
    const __half* srcB = B + bz * (long)K * N + n0;
    bias += bz * (long)N;

    float acc[4][4][4];
    #pragma unroll
    for (int a = 0; a < 4; a++)
        #pragma unroll
        for (int b = 0; b < 4; b++)
            #pragma unroll
            for (int c = 0; c < 4; c++) acc[a][b][c] = 0.f;

    const int NT = K / BK;

    auto load_stage = [&](int st, int kt) {
        const uint32_t stb = sbase + (uint32_t)st * STAGE_BYTES;
        // A tile: 128 rows x 128B (rows = m)
        {
            const __half* gA = srcA + kt + (tid & 7) * 8;
            #pragma unroll
            for (int i = 0; i < 4; i++) {
                int row = (tid >> 3) + i * 32;
                uint32_t sm = stb + (uint32_t)(row * 128 + (((tid & 7) ^ (row & 7)) << 4));
                CP_ASYNC16Z(sm, gA + atok[i], asz[i]);
            }
        }
        // B tile: 64 rows x 256B (rows = k, 128 fp16 n-cols per row)
        {
            const __half* gB = srcB + (size_t)kt * N + (tid & 15) * 8;
            const int r0 = tid >> 4;
            #pragma unroll
            for (int i = 0; i < 4; i++) {
                int row = r0 + i * 16;
                uint32_t sm = stb + A_TILE_BYTES +
                              (uint32_t)(row * 256 + (((tid & 15) ^ (row & 7)) << 4));
                CP_ASYNC16(sm, gB + (size_t)row * N);
            }
        }
    };

    // prime NSTAGE-1 stages
    #pragma unroll
    for (int p = 0; p < NSTAGE - 1; p++) {
        if (p < NT) { load_stage(p, p * BK); CP_COMMIT(); }
    }

    for (int s = 0; s < NT; s++) {
        if (s + NSTAGE - 1 < NT) CP_WAIT(NSTAGE - 2);
        else if (s + NSTAGE - 2 < NT) CP_WAIT(NSTAGE - 3);
        else CP_WAIT(0);
        // Single barrier per stage: orders (a) stage s data visible to all,
        // (b) all warps done computing stage s-1 before anyone overwrites
        // buffer (s+2)%3 (last read at stage s-1).
        __syncthreads();

        if (s + NSTAGE - 1 < NT) {
            load_stage((s + NSTAGE - 1) % NSTAGE, (s + NSTAGE - 1) * BK);
            CP_COMMIT();
        }

        const uint32_t stb = sbase + (uint32_t)(s % NSTAGE) * STAGE_BYTES;
        const uint32_t Ab = stb, Bb = stb + A_TILE_BYTES;

        const int g = lane >> 3;       // ldmatrix address group
        const int li = lane & 7;

        #pragma unroll
        for (int kk = 0; kk < 4; kk++) {
            uint32_t af[4][4];
            {
                const int arow_b = wm * 64 + (g & 1) * 8 + li;
                const int ach = kk * 2 + (g >> 1);
                #pragma unroll
                for (int mf = 0; mf < 4; mf++) {
                    int r = arow_b + mf * 16;
                    uint32_t off = (uint32_t)(r * 128 + ((ach ^ (r & 7)) << 4));
                    ldsm_x4(af[mf], Ab + off);
                }
            }
            uint32_t bf[4][2];
            {
                const int kr = kk * 16 + (g & 1) * 8 + li;
                #pragma unroll
                for (int nb = 0; nb < 2; nb++) {
                    const int c = wn * 4 + nb * 2 + (g >> 1);   // 16B chunk (8 fp16 cols)
                    uint32_t off = (uint32_t)(kr * 256 + ((c ^ (kr & 7)) << 4));
                    uint32_t t4[4];
                    ldsm_x4_t(t4, Bb + off);
                    bf[nb * 2][0] = t4[0]; bf[nb * 2][1] = t4[1];
                    bf[nb * 2 + 1][0] = t4[2]; bf[nb * 2 + 1][1] = t4[3];
                }
            }
            #pragma unroll
            for (int mf = 0; mf < 4; mf++)
                #pragma unroll
                for (int nf = 0; nf < 4; nf++)
                    mma16816(acc[mf][nf], af[mf], bf[nf]);
        }
    }

    // ---- epilogue ----
    const int mrow = m0 + wm * 64 + (lane >> 2);
    const int ncol0 = n0 + wn * 32 + (lane & 3) * 2;
    #pragma unroll
    for (int nf = 0; nf < 4; nf++) {
        const int n = ncol0 + nf * 8;
        const float bv0 = bias[n], bv1 = bias[n + 1];
        #pragma unroll
        for (int mf = 0; mf < 4; mf++) {
            const float* c = acc[mf][nf];
            const int m_a = mrow + mf * 16;
            const int m_b = m_a + 8;
            if (ACT == 1) {
                float v00 = gelu_tanh(c[0] + bv0), v01 = gelu_tanh(c[1] + bv1);
                float v10 = gelu_tanh(c[2] + bv0), v11 = gelu_tanh(c[3] + bv1);
                uint32_t p0 = (uint32_t)__half_as_ushort(__float2half_rn(v00)) |
                              ((uint32_t)__half_as_ushort(__float2half_rn(v01)) << 16);
                uint32_t p1 = (uint32_t)__half_as_ushort(__float2half_rn(v10)) |
                              ((uint32_t)__half_as_ushort(__float2half_rn(v11)) << 16);
                *(uint32_t*)(Ch + bz * (long)M * N + (size_t)m_a * N + n) = p0;
                *(uint32_t*)(Ch + bz * (long)M * N + (size_t)m_b * N + n) = p1;
            } else if (ACT == 0) {
                float2 r0 = make_float2(c[0] + bv0, c[1] + bv1);
                float2 r1 = make_float2(c[2] + bv0, c[3] + bv1);
                *(float2*)(Cf + bz * (long)M * N + (size_t)m_a * N + n) = r0;
                *(float2*)(Cf + bz * (long)M * N + (size_t)m_b * N + n) = r1;
            } else {
                #pragma unroll
                for (int h = 0; h < 2; h++) {
                    const int m = h ? m_b : m_a;
                    const float va = h ? (c[2] + bv0) : (c[0] + bv0);
                    const float vb = h ? (c[3] + bv1) : (c[1] + bv1);
                    const int dd = g_dest[m];
                    const float c0 = g_coef0[m];
                    const float c1g = g_coef1[m] * g_gate[m];
                    float2 xv = *(const float2*)(Xres + (size_t)m * N + n);
                    float2 ev = make_float2(0.f, 0.f);
                    if (dd >= 0) ev = *(const float2*)(Eo + (size_t)dd * N + n);
                    float2 o;
                    o.x = xv.x + c0 * va + c1g * ev.x;
                    o.y = xv.y + c0 * vb + c1g * ev.y;
                    *(float2*)(Cf + (size_t)m * N + n) = o;
                }
            }
        }
    }
}

template <int ACT, int GATHER>
__global__ __launch_bounds__(256, 2)
void mma_gemm(const __half* __restrict__ A, const __half* __restrict__ B,
              const float* __restrict__ bias,
              float* __restrict__ Cf, __half* __restrict__ Ch,
              const float* __restrict__ Xres, const float* __restrict__ Eo,
              int M, int N, int K) {
    gemm_body<ACT, GATHER>(A, B, bias, Cf, Ch, Xres, Eo, M, N, K,
                           blockIdx.x, blockIdx.y, blockIdx.z);
}

// ===========================================================================
// Merged middle launch: expert GEMM2 (512 CTAs, long-K, scheduled first) +
// res GEMM1 (2048 CTAs) — independent work fills eG2's wave tail.
// ===========================================================================
__global__ __launch_bounds__(256, 2)
void mid_gemm(const __half* __restrict__ h, const __half* __restrict__ ow,
              const float* __restrict__ out_b, float* __restrict__ eo,
              const __half* __restrict__ attn, const __half* __restrict__ ri,
              const float* __restrict__ ri_b, __half* __restrict__ rh) {
    int b = blockIdx.x;
    if (b < 512) {
        // expert GEMM2: grid (HID/BN=8, CAP/BM=8, NE=8)
        gemm_body<0, 0>(h, ow, out_b, eo, nullptr, nullptr, nullptr,
                        CAP, HID, INTR, b & 7, (b >> 3) & 7, b >> 6);
    } else {
        // res GEMM1: grid (INTR/BN=32, S_TOK/BM=64)
        b -= 512;
        gemm_body<1, 0>(attn, ri, ri_b, nullptr, rh, nullptr, nullptr,
                        S_TOK, INTR, HID, b & 31, b >> 5, 0);
    }
}

// ===========================================================================
extern "C" void kernel_launch(void* const* d_in, const int* in_sizes, int n_in,
                              void* d_out, int out_size) {
    const float* x       = (const float*)d_in[0];
    const float* attn_nw = (const float*)d_in[1];
    const float* attn_nb = (const float*)d_in[2];
    const float* wg      = (const float*)d_in[3];
    const float* inter_w = (const float*)d_in[4];
    const float* inter_b = (const float*)d_in[5];
    const float* out_w   = (const float*)d_in[6];
    const float* out_b   = (const float*)d_in[7];
    const float* ri_w    = (const float*)d_in[8];
    const float* ri_b    = (const float*)d_in[9];
    const float* ro_w    = (const float*)d_in[10];
    const float* ro_b    = (const float*)d_in[11];
    const float* rcoef   = (const float*)d_in[12];
    float* out = (float*)d_out;

    cudaFuncSetAttribute((const void*)mma_gemm<1, 1>, cudaFuncAttributeMaxDynamicSharedMemorySize, SMEM_BYTES);
    cudaFuncSetAttribute((const void*)mma_gemm<2, 0>, cudaFuncAttributeMaxDynamicSharedMemorySize, SMEM_BYTES);
    cudaFuncSetAttribute((const void*)mid_gemm,       cudaFuncAttributeMaxDynamicSharedMemorySize, SMEM_BYTES);

    void *p_h, *p_eo, *p_attn, *p_rh;
    void *p_iw, *p_ow, *p_ri, *p_ro;
    cudaGetSymbolAddress(&p_h, g_h);
    cudaGetSymbolAddress(&p_eo, g_eo);
    cudaGetSymbolAddress(&p_attn, g_attn);
    cudaGetSymbolAddress(&p_rh, g_rh);
    cudaGetSymbolAddress(&p_iw, g_iw);
    cudaGetSymbolAddress(&p_ow, g_ow);
    cudaGetSymbolAddress(&p_ri, g_ri);
    cudaGetSymbolAddress(&p_ro, g_ro);

    // minimal fork: wconv on side stream, overlapped ONLY with ln/scan on main
    // (R8/R14 showed overlapping memory kernels with the issue-bound GEMMs
    //  regresses; preamble-only overlap is the measured optimum)
    static cudaStream_t s2 = nullptr;
    static cudaEvent_t eF = nullptr, eW = nullptr;
    if (!s2) {
        cudaStreamCreateWithFlags(&s2, cudaStreamNonBlocking);
        cudaEventCreateWithFlags(&eF, cudaEventDisableTiming);
        cudaEventCreateWithFlags(&eW, cudaEventDisableTiming);
    }
    cudaEventRecord(eF, 0);
    cudaStreamWaitEvent(s2, eF, 0);
    wconv_all<<<IW_BLKS + OW_BLKS + RI_BLKS + RO_BLKS, 256, 0, s2>>>(
        inter_w, out_w, ri_w, ro_w);
    cudaEventRecord(eW, s2);

    ln_gate_kernel<<<S_TOK, 320>>>(x, attn_nw, attn_nb, wg, rcoef);
    scan_kernel<<<1, 256>>>();
    cudaStreamWaitEvent(0, eW, 0);   // join: all fp16 weights ready

    // expert GEMM1 + GELU with fused gather: h = gelu(attn[tos] @ iw + b)
    mma_gemm<1, 1><<<dim3(INTR / BN, CAP / BM, NE), 256, SMEM_BYTES>>>(
        (const __half*)p_attn, (const __half*)p_iw,
        inter_b, nullptr, (__half*)p_h, nullptr, nullptr, CAP, INTR, HID);
    // merged: expert GEMM2 (-> eo) + res GEMM1 (-> rh), independent work
    mid_gemm<<<512 + 2048, 256, SMEM_BYTES>>>(
        (const __half*)p_h, (const __half*)p_ow, out_b, (float*)p_eo,
        (const __half*)p_attn, (const __half*)p_ri, ri_b, (__half*)p_rh);
    // res GEMM2 + fused combine: out = x + c0*(rh@ro+b) + c1*gate*eo[dest]
    mma_gemm<2, 0><<<dim3(HID / BN, S_TOK / BM, 1), 256, SMEM_BYTES>>>(
        (const __half*)p_rh, (const __half*)p_ro,
        ro_b, out, nullptr, x, (const float*)p_eo, S_TOK, HID, INTR);
}